// round 2
// baseline (speedup 1.0000x reference)
#include <cuda_runtime.h>
#include <cuda_bf16.h>

#define N_NODES 100000
#define DIM     128
#define KNB     16

// Scratch: X1[n] = latents[n] @ W1[0:128,:] + b1 ; X2[n] = latents[n] @ W1[128:256,:]
__device__ float g_X1[(size_t)N_NODES * DIM];
__device__ float g_X2[(size_t)N_NODES * DIM];

// ---------------------------------------------------------------------------
// Kernel 1: GEMM  [100000 x 128] @ [128 x 128]  (x2 halves via blockIdx.y)
// BM=64, BN=128, BK=16, 128 threads, 8x8 register microtile per thread.
// ---------------------------------------------------------------------------
#define BM 64
#define BN 128
#define BK 16

__global__ __launch_bounds__(128) void mlp1_gemm(const float* __restrict__ lat,
                                                 const float* __restrict__ W1,
                                                 const float* __restrict__ b1) {
    const int half = blockIdx.y;
    const float* __restrict__ B = W1 + (half ? (DIM * DIM) : 0); // row-major [256][128]
    float* __restrict__ outp = half ? g_X2 : g_X1;
    const int m0 = blockIdx.x * BM;

    __shared__ float As[BK][BM + 4];   // transposed A tile, padded
    __shared__ float Bs[BK][BN];

    const int tid = threadIdx.x;           // 0..127
    const int tm  = (tid >> 4) * 8;        // 0..56
    const int tn  = (tid & 15) * 8;        // 0..120

    float acc[8][8];
#pragma unroll
    for (int i = 0; i < 8; i++)
#pragma unroll
        for (int j = 0; j < 8; j++) acc[i][j] = 0.f;

    for (int k0 = 0; k0 < DIM; k0 += BK) {
        // Load A tile: 64 rows x 16 k. 256 float4 total, 2 per thread. Store transposed.
#pragma unroll
        for (int t = 0; t < 2; t++) {
            int f  = tid * 2 + t;        // 0..255
            int m  = f >> 2;             // 0..63
            int kq = (f & 3) * 4;        // 0,4,8,12
            int gm = m0 + m;
            if (gm >= N_NODES) gm = N_NODES - 1;  // clamp (store is guarded)
            float4 v = *(const float4*)(lat + (size_t)gm * DIM + k0 + kq);
            As[kq + 0][m] = v.x;
            As[kq + 1][m] = v.y;
            As[kq + 2][m] = v.z;
            As[kq + 3][m] = v.w;
        }
        // Load B tile: 16 rows x 128 cols. 512 float4, 4 per thread.
#pragma unroll
        for (int t = 0; t < 4; t++) {
            int f  = tid * 4 + t;        // 0..511
            int kr = f >> 5;             // 0..15
            int c  = (f & 31) * 4;       // 0..124
            float4 v = *(const float4*)(B + (size_t)(k0 + kr) * DIM + c);
            *(float4*)(&Bs[kr][c]) = v;
        }
        __syncthreads();

#pragma unroll
        for (int k = 0; k < BK; k++) {
            float a[8], b[8];
            *(float4*)(a)     = *(const float4*)(&As[k][tm]);
            *(float4*)(a + 4) = *(const float4*)(&As[k][tm + 4]);
            *(float4*)(b)     = *(const float4*)(&Bs[k][tn]);
            *(float4*)(b + 4) = *(const float4*)(&Bs[k][tn + 4]);
#pragma unroll
            for (int i = 0; i < 8; i++)
#pragma unroll
                for (int j = 0; j < 8; j++)
                    acc[i][j] = fmaf(a[i], b[j], acc[i][j]);
        }
        __syncthreads();
    }

    // Epilogue: add bias (half 0 only), store.
    float bias[8];
#pragma unroll
    for (int j = 0; j < 8; j++) bias[j] = (half == 0) ? b1[tn + j] : 0.f;

#pragma unroll
    for (int i = 0; i < 8; i++) {
        int gm = m0 + tm + i;
        if (gm < N_NODES) {
            float4 v0, v1;
            v0.x = acc[i][0] + bias[0];
            v0.y = acc[i][1] + bias[1];
            v0.z = acc[i][2] + bias[2];
            v0.w = acc[i][3] + bias[3];
            v1.x = acc[i][4] + bias[4];
            v1.y = acc[i][5] + bias[5];
            v1.z = acc[i][6] + bias[6];
            v1.w = acc[i][7] + bias[7];
            float* o = outp + (size_t)gm * DIM + tn;
            *(float4*)(o)     = v0;
            *(float4*)(o + 4) = v1;
        }
    }
}

// ---------------------------------------------------------------------------
// Kernel 2: fused gather / score / softmax / weighted sum. One warp per node.
// score[n,k] = sum_d relu(X1[n,d] + X2[j,d]) * W2[d]   (b2 cancels in softmax)
// out[n]     = sum_k softmax(score)[k] * latents[j_k]
// NOTE: neighbors arrive as int32 (JAX default x64-disabled downcasts int64).
// ---------------------------------------------------------------------------
__global__ __launch_bounds__(256) void attend_kernel(const float* __restrict__ lat,
                                                     const int* __restrict__ nbr,
                                                     const float* __restrict__ W2,
                                                     float* __restrict__ out) {
    __shared__ float s_w2[DIM];
    const int tid = threadIdx.x;
    if (tid < DIM) s_w2[tid] = W2[tid];
    __syncthreads();

    const int n = blockIdx.x * (blockDim.x >> 5) + (tid >> 5);
    if (n >= N_NODES) return;
    const int lane = tid & 31;

    const float4 x1  = *(const float4*)(g_X1 + (size_t)n * DIM + lane * 4);
    const float4 w2v = *(const float4*)(s_w2 + lane * 4);

    int js[KNB];
    {
        // 16 int32 indices = 4 x int4 (row is 64B aligned), lane-redundant but L1-hit.
        const int4* p = (const int4*)(nbr + (size_t)n * KNB);
#pragma unroll
        for (int q = 0; q < 4; q++) {
            int4 v = __ldg(p + q);
            js[q * 4 + 0] = v.x;
            js[q * 4 + 1] = v.y;
            js[q * 4 + 2] = v.z;
            js[q * 4 + 3] = v.w;
        }
    }

    float  sc[KNB];
    float4 lb[KNB];
#pragma unroll
    for (int k = 0; k < KNB; k++) {
        const size_t off = (size_t)js[k] * DIM + lane * 4;
        const float4 x2 = *(const float4*)(g_X2 + off);
        const float4 lv = __ldg((const float4*)(lat + off));
        lb[k] = lv;
        float p = fmaxf(x1.x + x2.x, 0.f) * w2v.x;
        p = fmaf(fmaxf(x1.y + x2.y, 0.f), w2v.y, p);
        p = fmaf(fmaxf(x1.z + x2.z, 0.f), w2v.z, p);
        p = fmaf(fmaxf(x1.w + x2.w, 0.f), w2v.w, p);
        sc[k] = p;
    }

    // Warp-reduce each of the 16 scores (result in all lanes).
#pragma unroll
    for (int k = 0; k < KNB; k++) {
        float p = sc[k];
        p += __shfl_xor_sync(0xffffffffu, p, 16);
        p += __shfl_xor_sync(0xffffffffu, p, 8);
        p += __shfl_xor_sync(0xffffffffu, p, 4);
        p += __shfl_xor_sync(0xffffffffu, p, 2);
        p += __shfl_xor_sync(0xffffffffu, p, 1);
        sc[k] = p;
    }

    // Softmax over K=16 (redundant per-lane, cheap).
    float m = sc[0];
#pragma unroll
    for (int k = 1; k < KNB; k++) m = fmaxf(m, sc[k]);
    float s = 0.f;
#pragma unroll
    for (int k = 0; k < KNB; k++) {
        sc[k] = __expf(sc[k] - m);
        s += sc[k];
    }
    const float inv = 1.f / s;

    float4 acc = make_float4(0.f, 0.f, 0.f, 0.f);
#pragma unroll
    for (int k = 0; k < KNB; k++) {
        const float w = sc[k] * inv;
        acc.x = fmaf(w, lb[k].x, acc.x);
        acc.y = fmaf(w, lb[k].y, acc.y);
        acc.z = fmaf(w, lb[k].z, acc.z);
        acc.w = fmaf(w, lb[k].w, acc.w);
    }
    *(float4*)(out + (size_t)n * DIM + lane * 4) = acc;
}

// ---------------------------------------------------------------------------
// Launch
// ---------------------------------------------------------------------------
extern "C" void kernel_launch(void* const* d_in, const int* in_sizes, int n_in,
                              void* d_out, int out_size) {
    const float* latents   = (const float*)d_in[0];
    const int*   neighbors = (const int*)d_in[1];   // int32 (JAX x64-disabled)
    const float* W1        = (const float*)d_in[2];
    const float* b1        = (const float*)d_in[3];
    const float* W2        = (const float*)d_in[4];
    // d_in[5] = b2: constant shift across softmax axis -> cancels, unused.
    float* out = (float*)d_out;

    (void)in_sizes; (void)n_in; (void)out_size;

    dim3 ggrid((N_NODES + BM - 1) / BM, 2);
    mlp1_gemm<<<ggrid, 128>>>(latents, W1, b1);

    const int warps_per_block = 8;
    const int blocks = (N_NODES + warps_per_block - 1) / warps_per_block;
    attend_kernel<<<blocks, warps_per_block * 32>>>(latents, neighbors, W2, out);
}